// round 2
// baseline (speedup 1.0000x reference)
#include <cuda_runtime.h>
#include <math.h>

// ---------------------------------------------------------------------------
// Problem constants
// ---------------------------------------------------------------------------
#define GB   128            // graphs
#define NPG  1024           // nodes per graph (layer 1)
#define NE   1048576        // total edges
#define NT1  131072         // 128*1024
#define K1   820            // ceil(0.8*1024)
#define NT2  104960         // 128*820
#define K2   656            // ceil(0.8*820)
#define NT3  83968          // 128*656
#define K3   525            // ceil(0.8*656)
#define NT4  67200          // 128*525

// ---------------------------------------------------------------------------
// Scratch (static device memory only — no allocations allowed)
// ---------------------------------------------------------------------------
__device__ float g_bufA[NT1 * 64];   // pooled features (conv input for layers 2/3)
__device__ float g_bufB[NT1 * 64];   // xw = h @ W
__device__ float g_bufC[NT1 * 64];   // conv output (post-relu)
__device__ float g_sw[NT1];          // h . Wp  per node
__device__ float g_score[NT1];
__device__ float g_dis[NT1];         // rsqrt(deg+1)
__device__ int   g_deg[NT1];
__device__ int   g_rowptr[NT1];
__device__ int   g_cursor[NT1];
__device__ int   g_newidx[NT1];
__device__ int   g_perm[NT2];
__device__ int   g_slots[NE];
__device__ int   g_srcA[NE], g_dstA[NE];
__device__ int   g_srcB[NE], g_dstB[NE];
__device__ int   g_ecount[2];
__device__ int   g_bsums[512];
__device__ float g_z[GB * 128];

// ---------------------------------------------------------------------------
// Helpers
// ---------------------------------------------------------------------------
__device__ __forceinline__ const int* pick_list_src(const int* p, int sel) {
    return p ? p : (sel ? g_srcB : g_srcA);
}
__device__ __forceinline__ const int* pick_list_dst(const int* p, int sel) {
    return p ? p : (sel ? g_dstB : g_dstA);
}

// ---------------------------------------------------------------------------
// Small utility kernels
// ---------------------------------------------------------------------------
__global__ void k_clear_deg(int n) {
    int i = blockIdx.x * blockDim.x + threadIdx.x;
    if (i < n) g_deg[i] = 0;
}

// degree count (dst side), grid-stride with runtime count
__global__ void k_deg(const int* dstp, int sel, int cw, int fixcnt) {
    const int* __restrict__ dst = pick_list_dst(dstp, sel);
    int cnt = (cw >= 0) ? g_ecount[cw] : fixcnt;
    int stride = gridDim.x * blockDim.x;
    for (int i = blockIdx.x * blockDim.x + threadIdx.x; i < cnt; i += stride)
        atomicAdd(&g_deg[dst[i]], 1);
}

// block-local exclusive scan of deg (256 per block)
__global__ void k_scan1() {
    __shared__ int s[256];
    int b = blockIdx.x, t = threadIdx.x;
    s[t] = g_deg[b * 256 + t];
    __syncthreads();
    for (int d = 1; d < 256; d <<= 1) {
        int i = (t + 1) * (d << 1) - 1;
        if (i < 256) s[i] += s[i - d];
        __syncthreads();
    }
    if (t == 0) { g_bsums[b] = s[255]; s[255] = 0; }
    __syncthreads();
    for (int d = 128; d >= 1; d >>= 1) {
        int i = (t + 1) * (d << 1) - 1;
        if (i < 256) { int tmp = s[i - d]; s[i - d] = s[i]; s[i] += tmp; }
        __syncthreads();
    }
    g_rowptr[b * 256 + t] = s[t];
}

// exclusive scan of block sums (single block, 512 threads)
__global__ void k_scan2(int nb) {
    __shared__ int s[512];
    int t = threadIdx.x;
    s[t] = (t < nb) ? g_bsums[t] : 0;
    __syncthreads();
    for (int d = 1; d < 512; d <<= 1) {
        int i = (t + 1) * (d << 1) - 1;
        if (i < 512) s[i] += s[i - d];
        __syncthreads();
    }
    if (t == 0) s[511] = 0;
    __syncthreads();
    for (int d = 256; d >= 1; d >>= 1) {
        int i = (t + 1) * (d << 1) - 1;
        if (i < 512) { int tmp = s[i - d]; s[i - d] = s[i]; s[i] += tmp; }
        __syncthreads();
    }
    if (t < nb) g_bsums[t] = s[t];
}

// add block offsets; init cursor; dis = rsqrt(deg+1)
__global__ void k_scan3(int n) {
    int i = blockIdx.x * blockDim.x + threadIdx.x;
    if (i < n) {
        int rp = g_rowptr[i] + g_bsums[i >> 8];
        g_rowptr[i] = rp;
        g_cursor[i] = rp;
        g_dis[i] = rsqrtf((float)(g_deg[i] + 1));
    }
}

// CSR fill: slot per (dst) position gets src id
__global__ void k_fill(const int* srcp, const int* dstp, int sel, int cw, int fixcnt) {
    const int* __restrict__ src = pick_list_src(srcp, sel);
    const int* __restrict__ dst = pick_list_dst(dstp, sel);
    int cnt = (cw >= 0) ? g_ecount[cw] : fixcnt;
    int stride = gridDim.x * blockDim.x;
    for (int i = blockIdx.x * blockDim.x + threadIdx.x; i < cnt; i += stride) {
        int p = atomicAdd(&g_cursor[dst[i]], 1);
        g_slots[p] = src[i];
    }
}

// ---------------------------------------------------------------------------
// GEMM: Y(bufB) = X @ W,  X is M x 64, W is 64 x 64, M divisible by 64
// block = 128 threads, tile = 64 rows, each thread computes 4 rows x 8 cols
// ---------------------------------------------------------------------------
__global__ __launch_bounds__(128) void k_gemm(const float* __restrict__ Xp,
                                              const float* __restrict__ W, int M) {
    __shared__ __align__(16) float Xs[64][65];
    __shared__ __align__(16) float Ws[64][64];
    const float* X = Xp ? Xp : g_bufA;
    int t = threadIdx.x;
    int rowBase = blockIdx.x * 64;

    // load W (4096 floats) as float4
#pragma unroll
    for (int k = 0; k < 8; k++) {
        int idx = k * 128 + t;
        ((float4*)&Ws[0][0])[idx] = ((const float4*)W)[idx];
    }
    // load X tile (64 rows x 64 floats) as float4
#pragma unroll
    for (int k = 0; k < 8; k++) {
        int idx = k * 128 + t;       // float4 index, 1024 total
        int r = idx >> 4;            // 16 float4 per row
        int c4 = idx & 15;
        float4 v = ((const float4*)(X + (size_t)(rowBase + r) * 64))[c4];
        Xs[r][c4 * 4 + 0] = v.x; Xs[r][c4 * 4 + 1] = v.y;
        Xs[r][c4 * 4 + 2] = v.z; Xs[r][c4 * 4 + 3] = v.w;
    }
    __syncthreads();

    int r0 = (t >> 3) * 4;
    int c0 = (t & 7) * 8;
    float acc[4][8];
#pragma unroll
    for (int i = 0; i < 4; i++)
#pragma unroll
        for (int j = 0; j < 8; j++) acc[i][j] = 0.f;

#pragma unroll 8
    for (int k = 0; k < 64; k++) {
        float av[4];
        av[0] = Xs[r0 + 0][k]; av[1] = Xs[r0 + 1][k];
        av[2] = Xs[r0 + 2][k]; av[3] = Xs[r0 + 3][k];
        float4 w0 = *(const float4*)&Ws[k][c0];
        float4 w1 = *(const float4*)&Ws[k][c0 + 4];
        float wv[8] = {w0.x, w0.y, w0.z, w0.w, w1.x, w1.y, w1.z, w1.w};
#pragma unroll
        for (int i = 0; i < 4; i++)
#pragma unroll
            for (int j = 0; j < 8; j++) acc[i][j] += av[i] * wv[j];
    }

#pragma unroll
    for (int i = 0; i < 4; i++) {
        float* out = g_bufB + (size_t)(rowBase + r0 + i) * 64 + c0;
        *(float4*)(out + 0) = make_float4(acc[i][0], acc[i][1], acc[i][2], acc[i][3]);
        *(float4*)(out + 4) = make_float4(acc[i][4], acc[i][5], acc[i][6], acc[i][7]);
    }
}

// ---------------------------------------------------------------------------
// GCN aggregation: warp per dst node.
//   h[d] = relu( dis[d]*sum_e xw[src_e]*dis[src_e] + xw[d]*dis[d]^2 + b )
// Fused epilogue: sw[d] = h[d] . Wp
// ---------------------------------------------------------------------------
__global__ __launch_bounds__(256) void k_conv(const float* __restrict__ bias,
                                              const float* __restrict__ Wp, int ntot) {
    int w = (blockIdx.x * blockDim.x + threadIdx.x) >> 5;
    int lane = threadIdx.x & 31;
    if (w >= ntot) return;
    int start = g_rowptr[w], len = g_deg[w];
    const float2* __restrict__ xw2 = (const float2*)g_bufB;
    float2 acc = make_float2(0.f, 0.f);
    int s = (len > 0) ? g_slots[start] : 0;
    for (int e = 0; e < len; e++) {
        int snext = (e + 1 < len) ? g_slots[start + e + 1] : 0;
        float ds = g_dis[s];
        float2 v = xw2[(size_t)s * 32 + lane];
        acc.x += v.x * ds; acc.y += v.y * ds;
        s = snext;
    }
    float dd = g_dis[w];
    float2 self = xw2[(size_t)w * 32 + lane];
    float hx = fmaxf(acc.x * dd + self.x * dd * dd + bias[2 * lane], 0.f);
    float hy = fmaxf(acc.y * dd + self.y * dd * dd + bias[2 * lane + 1], 0.f);
    ((float2*)g_bufC)[(size_t)w * 32 + lane] = make_float2(hx, hy);
    // fused sw = h . Wp
    float p = hx * Wp[2 * lane] + hy * Wp[2 * lane + 1];
#pragma unroll
    for (int o = 16; o > 0; o >>= 1) p += __shfl_down_sync(0xffffffffu, p, o);
    if (lane == 0) g_sw[w] = p;
}

// score aggregation (scalar): thread per node
__global__ void k_score(const float* __restrict__ bp, int ntot) {
    int i = blockIdx.x * blockDim.x + threadIdx.x;
    if (i >= ntot) return;
    int start = g_rowptr[i], len = g_deg[i];
    float s = 0.f;
    for (int e = 0; e < len; e++) {
        int sr = g_slots[start + e];
        s += g_sw[sr] * g_dis[sr];
    }
    float d = g_dis[i];
    g_score[i] = d * s + g_sw[i] * d * d + bp[0];
}

// ---------------------------------------------------------------------------
// Per-graph top-k set selection + compaction. One block (512 thr) per graph.
// Matches jax.lax.top_k set semantics incl. index-order tie-break at threshold.
// Also zeroes g_ecount[ec_clear] (block 0) for the following remap step.
// ---------------------------------------------------------------------------
__device__ __forceinline__ void scan1024_excl(int* s) {
    int t = threadIdx.x;
    for (int d = 1; d < 1024; d <<= 1) {
        int i = (t + 1) * (d << 1) - 1;
        if (i < 1024) s[i] += s[i - d];
        __syncthreads();
    }
    if (t == 0) s[1023] = 0;
    __syncthreads();
    for (int d = 512; d >= 1; d >>= 1) {
        int i = (t + 1) * (d << 1) - 1;
        if (i < 1024) { int tmp = s[i - d]; s[i - d] = s[i]; s[i] += tmp; }
        __syncthreads();
    }
}

__global__ __launch_bounds__(512) void k_select(int ncur, int ksel, int ec_clear) {
    __shared__ float ssort[1024];
    __shared__ float sorig[1024];
    __shared__ int   sscan[1024];
    __shared__ int   s_g;
    int g = blockIdx.x, t = threadIdx.x;
    if (ec_clear >= 0 && g == 0 && t == 0) g_ecount[ec_clear] = 0;
    int base = g * ncur;
    for (int i = t; i < 1024; i += 512) {
        float v = (i < ncur) ? g_score[base + i] : -INFINITY;
        ssort[i] = v; sorig[i] = v;
    }
    if (t == 0) s_g = 0;
    __syncthreads();
    // bitonic sort descending (1024 elements)
    for (int kk = 2; kk <= 1024; kk <<= 1) {
        for (int j = kk >> 1; j > 0; j >>= 1) {
            for (int i = t; i < 1024; i += 512) {
                int ixj = i ^ j;
                if (ixj > i) {
                    float a = ssort[i], b = ssort[ixj];
                    bool up = ((i & kk) == 0);      // descending overall
                    if (up ? (a < b) : (a > b)) { ssort[i] = b; ssort[ixj] = a; }
                }
            }
            __syncthreads();
        }
    }
    float thr = ssort[ksel - 1];
    // count strictly greater than thr
    int cg = 0;
    for (int i = t; i < 1024; i += 512) if (sorig[i] > thr) cg++;
    atomicAdd(&s_g, cg);
    __syncthreads();
    int need_eq = ksel - s_g;
    // exclusive scan of equality flags (index order)
    for (int i = t; i < 1024; i += 512)
        sscan[i] = (i < ncur && sorig[i] == thr) ? 1 : 0;
    __syncthreads();
    scan1024_excl(sscan);
    int i0 = t, i1 = t + 512;
    float v0 = sorig[i0], v1 = sorig[i1];
    int sel0 = (i0 < ncur) && (v0 > thr || (v0 == thr && sscan[i0] < need_eq));
    int sel1 = (i1 < ncur) && (v1 > thr || (v1 == thr && sscan[i1] < need_eq));
    __syncthreads();
    sscan[i0] = sel0; sscan[i1] = sel1;
    __syncthreads();
    scan1024_excl(sscan);
    if (i0 < ncur) {
        int old = base + i0;
        if (sel0) { int np = g * ksel + sscan[i0]; g_newidx[old] = np; g_perm[np] = old; }
        else g_newidx[old] = -1;
    }
    if (i1 < ncur) {
        int old = base + i1;
        if (sel1) { int np = g * ksel + sscan[i1]; g_newidx[old] = np; g_perm[np] = old; }
        else g_newidx[old] = -1;
    }
}

// gather pooled features: bufA[new] = bufC[old] * tanh(score[old]); warp/node
// Also zeroes g_deg for the next layer's node set (exactly nnew nodes).
__global__ __launch_bounds__(256) void k_pool(int nnew) {
    int w = (blockIdx.x * blockDim.x + threadIdx.x) >> 5;
    int lane = threadIdx.x & 31;
    if (w >= nnew) return;
    if (lane == 0) g_deg[w] = 0;
    int old = g_perm[w];
    float tg = tanhf(g_score[old]);
    float2 v = ((const float2*)g_bufC)[(size_t)old * 32 + lane];
    ((float2*)g_bufA)[(size_t)w * 32 + lane] = make_float2(v.x * tg, v.y * tg);
}

// readout: per graph max & mean over k rows of bufA -> z (write or accumulate)
__global__ __launch_bounds__(256) void k_readout(int krows, int acc) {
    int g = blockIdx.x, t = threadIdx.x;
    int f = t & 63, ry = t >> 6;
    float mx = -INFINITY, sm = 0.f;
    const float* base = g_bufA + (size_t)g * krows * 64;
    for (int r = ry; r < krows; r += 4) {
        float v = base[(size_t)r * 64 + f];
        mx = fmaxf(mx, v); sm += v;
    }
    __shared__ float smx[4][64], ssm[4][64];
    smx[ry][f] = mx; ssm[ry][f] = sm;
    __syncthreads();
    if (ry == 0) {
        mx = fmaxf(fmaxf(smx[0][f], smx[1][f]), fmaxf(smx[2][f], smx[3][f]));
        sm = ssm[0][f] + ssm[1][f] + ssm[2][f] + ssm[3][f];
        float mean = sm / (float)krows;
        if (acc) { g_z[g * 128 + f] += mx; g_z[g * 128 + 64 + f] += mean; }
        else     { g_z[g * 128 + f]  = mx; g_z[g * 128 + 64 + f]  = mean; }
    }
}

// remap + compact edges for next layer
__global__ void k_remap(const int* srcp, const int* dstp, int insel,
                        int cw, int fixcnt, int outsel) {
    const int* __restrict__ src = pick_list_src(srcp, insel);
    const int* __restrict__ dst = pick_list_dst(dstp, insel);
    int* os = outsel ? g_srcB : g_srcA;
    int* od = outsel ? g_dstB : g_dstA;
    int cnt = (cw >= 0) ? g_ecount[cw] : fixcnt;
    int stride = gridDim.x * blockDim.x;
    for (int i = blockIdx.x * blockDim.x + threadIdx.x; i < cnt; i += stride) {
        int ns = g_newidx[src[i]];
        int nd = g_newidx[dst[i]];
        if ((ns | nd) >= 0) {
            int p = atomicAdd(&g_ecount[outsel], 1);
            os[p] = ns; od[p] = nd;
        }
    }
}

// MLP head + log_softmax, one block (128 thr) per graph
__global__ __launch_bounds__(128) void k_mlp(const float* __restrict__ L1w,
                                             const float* __restrict__ L1b,
                                             const float* __restrict__ L2w,
                                             const float* __restrict__ L2b,
                                             const float* __restrict__ L3w,
                                             const float* __restrict__ L3b,
                                             float* __restrict__ out) {
    int g = blockIdx.x, t = threadIdx.x;
    __shared__ float zs[128], h1[64], h2[32], lg[10], lse;
    zs[t] = g_z[g * 128 + t];
    __syncthreads();
    if (t < 64) {
        float a = L1b[t];
        for (int k = 0; k < 128; k++) a += zs[k] * L1w[k * 64 + t];
        h1[t] = fmaxf(a, 0.f);
    }
    __syncthreads();
    if (t < 32) {
        float a = L2b[t];
        for (int k = 0; k < 64; k++) a += h1[k] * L2w[k * 32 + t];
        h2[t] = fmaxf(a, 0.f);
    }
    __syncthreads();
    if (t < 10) {
        float a = L3b[t];
        for (int k = 0; k < 32; k++) a += h2[k] * L3w[k * 10 + t];
        lg[t] = a;
    }
    __syncthreads();
    if (t == 0) {
        float m = lg[0];
        for (int i = 1; i < 10; i++) m = fmaxf(m, lg[i]);
        float s = 0.f;
        for (int i = 0; i < 10; i++) s += expf(lg[i] - m);
        lse = m + logf(s);
    }
    __syncthreads();
    if (t < 10) out[g * 10 + t] = lg[t] - lse;
}

// ---------------------------------------------------------------------------
// Host orchestration
// ---------------------------------------------------------------------------
extern "C" void kernel_launch(void* const* d_in, const int* in_sizes, int n_in,
                              void* d_out, int out_size) {
    const float* x    = (const float*)d_in[0];
    const int*   esrc = (const int*)d_in[1];
    const int*   edst = (const int*)d_in[2];
    const float* W1  = (const float*)d_in[3];
    const float* b1  = (const float*)d_in[4];
    const float* Wp1 = (const float*)d_in[5];
    const float* bp1 = (const float*)d_in[6];
    const float* W2  = (const float*)d_in[7];
    const float* b2  = (const float*)d_in[8];
    const float* Wp2 = (const float*)d_in[9];
    const float* bp2 = (const float*)d_in[10];
    const float* W3  = (const float*)d_in[11];
    const float* b3  = (const float*)d_in[12];
    const float* Wp3 = (const float*)d_in[13];
    const float* bp3 = (const float*)d_in[14];
    const float* L1w = (const float*)d_in[15];
    const float* L1b = (const float*)d_in[16];
    const float* L2w = (const float*)d_in[17];
    const float* L2b = (const float*)d_in[18];
    const float* L3w = (const float*)d_in[19];
    const float* L3b = (const float*)d_in[20];
    float* out = (float*)d_out;

    const int EG = 2048;   // grid for edge-parallel kernels (grid-stride)

    // ---------------- Layer 1 (n=1024, edges: original, count NE) ----------
    k_clear_deg<<<NT1 / 256, 256>>>(NT1);
    k_deg<<<EG, 256>>>(edst, 0, -1, NE);
    k_scan1<<<NT1 / 256, 256>>>();
    k_scan2<<<1, 512>>>(NT1 / 256);
    k_scan3<<<NT1 / 256, 256>>>(NT1);
    k_fill<<<EG, 256>>>(esrc, edst, 0, -1, NE);
    k_gemm<<<NT1 / 64, 128>>>(x, W1, NT1);
    k_conv<<<NT1 / 8, 256>>>(b1, Wp1, NT1);
    k_score<<<NT1 / 256, 256>>>(bp1, NT1);
    k_select<<<GB, 512>>>(NPG, K1, 0);
    k_pool<<<NT2 / 8, 256>>>(NT2);       // also clears g_deg[0..NT2)
    k_readout<<<GB, 256>>>(K1, 0);
    k_remap<<<EG, 256>>>(esrc, edst, 0, -1, NE, 0);

    // ---------------- Layer 2 (n=820, edges: list A, count ecount[0]) ------
    k_deg<<<EG, 256>>>(nullptr, 0, 0, 0);
    k_scan1<<<NT2 / 256, 256>>>();
    k_scan2<<<1, 512>>>(NT2 / 256);
    k_scan3<<<NT2 / 256, 256>>>(NT2);
    k_fill<<<EG, 256>>>(nullptr, nullptr, 0, 0, 0);
    k_gemm<<<NT2 / 64, 128>>>(nullptr, W2, NT2);
    k_conv<<<NT2 / 8, 256>>>(b2, Wp2, NT2);
    k_score<<<NT2 / 256, 256>>>(bp2, NT2);
    k_select<<<GB, 512>>>(K1, K2, 1);
    k_pool<<<NT3 / 8, 256>>>(NT3);       // also clears g_deg[0..NT3)
    k_readout<<<GB, 256>>>(K2, 1);
    k_remap<<<EG, 256>>>(nullptr, nullptr, 0, 0, 0, 1);

    // ---------------- Layer 3 (n=656, edges: list B, count ecount[1]) ------
    k_deg<<<EG, 256>>>(nullptr, 1, 1, 0);
    k_scan1<<<NT3 / 256, 256>>>();
    k_scan2<<<1, 512>>>(NT3 / 256);
    k_scan3<<<NT3 / 256, 256>>>(NT3);
    k_fill<<<EG, 256>>>(nullptr, nullptr, 1, 1, 0);
    k_gemm<<<NT3 / 64, 128>>>(nullptr, W3, NT3);
    k_conv<<<NT3 / 8, 256>>>(b3, Wp3, NT3);
    k_score<<<NT3 / 256, 256>>>(bp3, NT3);
    k_select<<<GB, 512>>>(K2, K3, -1);
    k_pool<<<NT4 / 8, 256>>>(NT4);
    k_readout<<<GB, 256>>>(K3, 1);

    // ---------------- MLP head + log_softmax ------------------------------
    k_mlp<<<GB, 128>>>(L1w, L1b, L2w, L2b, L3w, L3b, out);
}

// round 7
// speedup vs baseline: 1.0851x; 1.0851x over previous
#include <cuda_runtime.h>
#include <math.h>

// ---------------------------------------------------------------------------
// Problem constants
// ---------------------------------------------------------------------------
#define GB   128            // graphs
#define NPG  1024           // nodes per graph (layer 1)
#define NE   1048576        // total edges
#define NT1  131072         // 128*1024
#define K1   820            // ceil(0.8*1024)
#define NT2  104960         // 128*820
#define K2   656            // ceil(0.8*820)
#define NT3  83968          // 128*656
#define K3   525            // ceil(0.8*656)
#define NT4  67200          // 128*525

// ---------------------------------------------------------------------------
// Scratch (static device memory only — no allocations allowed)
// ---------------------------------------------------------------------------
__device__ float  g_bufA[NT1 * 64];   // pooled features (conv input for layers 2/3)
__device__ float  g_bufB[NT1 * 64];   // xw = h @ W
__device__ float  g_bufC[NT1 * 64];   // conv output (post-relu)
__device__ float2 g_swdis[NT1];       // (h.Wp, dis) per node
__device__ float  g_tanh[NT2];        // tanh(score) of selected nodes (new idx)
__device__ float  g_dis[NT1];         // rsqrt(deg+1)
__device__ int    g_deg[NT1];
__device__ int    g_rowptr[NT1];
__device__ int    g_cursor[NT1];
__device__ int    g_newidx[NT1];
__device__ int    g_perm[NT2];
__device__ int    g_slots[NE];
__device__ int    g_srcA[NE], g_dstA[NE];
__device__ int    g_srcB[NE], g_dstB[NE];
__device__ int    g_ecount[2];
__device__ float  g_z[GB * 128];
// decoupled-lookback scan state
__device__ unsigned g_tstate[256];
__device__ int      g_tix;

// ---------------------------------------------------------------------------
// Helpers
// ---------------------------------------------------------------------------
__device__ __forceinline__ const int* pick_list_src(const int* p, int sel) {
    return p ? p : (sel ? g_srcB : g_srcA);
}
__device__ __forceinline__ const int* pick_list_dst(const int* p, int sel) {
    return p ? p : (sel ? g_dstB : g_dstA);
}

// ---------------------------------------------------------------------------
// Layer-1 init: clear deg + scan state
// ---------------------------------------------------------------------------
__global__ void k_clear() {
    int i = blockIdx.x * blockDim.x + threadIdx.x;
    if (i < NT1) g_deg[i] = 0;
    if (i < 256) g_tstate[i] = 0;
    if (i == 256) g_tix = 0;
}

// degree count (dst side) for layer 1 only
__global__ void k_deg(const int* __restrict__ dst, int cnt) {
    int stride = gridDim.x * blockDim.x;
    for (int i = blockIdx.x * blockDim.x + threadIdx.x; i < cnt; i += stride)
        atomicAdd(&g_deg[dst[i]], 1);
}

// ---------------------------------------------------------------------------
// Single-pass exclusive scan of g_deg[0..n) -> rowptr/cursor, dis=rsqrt(deg+1)
// Decoupled lookback, 1024 elements per tile (256 thr x 4). grid = #tiles.
// Requires g_tstate[] and g_tix zeroed beforehand.
// ---------------------------------------------------------------------------
__global__ __launch_bounds__(256) void k_scan(int n) {
    __shared__ int s_tile;
    __shared__ int s_wsum[8];
    __shared__ int s_off;
    int t = threadIdx.x;
    if (t == 0) s_tile = atomicAdd(&g_tix, 1);
    __syncthreads();
    int tile = s_tile;
    int base = tile * 1024 + t * 4;
    int v[4];
#pragma unroll
    for (int i = 0; i < 4; i++) {
        int idx = base + i;
        v[i] = (idx < n) ? g_deg[idx] : 0;
    }
    int tsum = v[0] + v[1] + v[2] + v[3];
    int lane = t & 31, wid = t >> 5;
    int inc = tsum;
#pragma unroll
    for (int o = 1; o < 32; o <<= 1) {
        int u = __shfl_up_sync(0xffffffffu, inc, o);
        if (lane >= o) inc += u;
    }
    if (lane == 31) s_wsum[wid] = inc;
    __syncthreads();
    if (wid == 0) {
        int ws = (lane < 8) ? s_wsum[lane] : 0;
#pragma unroll
        for (int o = 1; o < 8; o <<= 1) {
            int u = __shfl_up_sync(0xffffffffu, ws, o);
            if (lane >= o) ws += u;
        }
        if (lane < 8) s_wsum[lane] = ws;   // inclusive warp sums
    }
    __syncthreads();
    int blockAgg = s_wsum[7];
    int excl = inc - tsum + (wid > 0 ? s_wsum[wid - 1] : 0);

    if (t == 0) {
        unsigned val = (tile == 0) ? (((unsigned)blockAgg << 2) | 2u)
                                   : (((unsigned)blockAgg << 2) | 1u);
        __threadfence();
        atomicExch(&g_tstate[tile], val);
    }
    if (wid == 0) {
        int offset = 0;
        if (tile > 0) {
            int tb = tile - 1;
            while (true) {
                int idx = tb - lane;
                unsigned s;
                while (true) {
                    s = (idx >= 0) ? atomicAdd(&g_tstate[idx], 0u) : 2u;
                    if (!__any_sync(0xffffffffu, (s & 3u) == 0u)) break;
                }
                unsigned bal = __ballot_sync(0xffffffffu, (s & 3u) == 2u);
                int c;
                if (bal) {
                    int fp = __ffs(bal) - 1;
                    c = (lane <= fp) ? (int)(s >> 2) : 0;
                } else {
                    c = (idx >= 0) ? (int)(s >> 2) : 0;
                }
#pragma unroll
                for (int o = 16; o > 0; o >>= 1) c += __shfl_down_sync(0xffffffffu, c, o);
                c = __shfl_sync(0xffffffffu, c, 0);
                offset += c;
                if (bal) break;
                tb -= 32;
            }
        }
        if (lane == 0) {
            s_off = offset;
            if (tile > 0) {
                __threadfence();
                atomicExch(&g_tstate[tile], (((unsigned)(offset + blockAgg)) << 2) | 2u);
            }
        }
    }
    __syncthreads();
    int run = s_off + excl;
#pragma unroll
    for (int i = 0; i < 4; i++) {
        int idx = base + i;
        if (idx < n) {
            g_rowptr[idx] = run;
            g_cursor[idx] = run;
            g_dis[idx] = rsqrtf((float)(v[i] + 1));
            run += v[i];
        }
    }
}

// CSR fill: slot per (dst) position gets src id
__global__ void k_fill(const int* srcp, const int* dstp, int sel, int cw, int fixcnt) {
    const int* __restrict__ src = pick_list_src(srcp, sel);
    const int* __restrict__ dst = pick_list_dst(dstp, sel);
    int cnt = (cw >= 0) ? g_ecount[cw] : fixcnt;
    int stride = gridDim.x * blockDim.x;
    for (int i = blockIdx.x * blockDim.x + threadIdx.x; i < cnt; i += stride) {
        int p = atomicAdd(&g_cursor[dst[i]], 1);
        g_slots[p] = src[i];
    }
}

// ---------------------------------------------------------------------------
// GEMM: Y(bufB) = X @ W,  X is M x 64, W is 64 x 64, M divisible by 64
// ---------------------------------------------------------------------------
__global__ __launch_bounds__(128) void k_gemm(const float* __restrict__ Xp,
                                              const float* __restrict__ W, int M) {
    __shared__ __align__(16) float Xs[64][65];
    __shared__ __align__(16) float Ws[64][64];
    const float* X = Xp ? Xp : g_bufA;
    int t = threadIdx.x;
    int rowBase = blockIdx.x * 64;

#pragma unroll
    for (int k = 0; k < 8; k++) {
        int idx = k * 128 + t;
        ((float4*)&Ws[0][0])[idx] = ((const float4*)W)[idx];
    }
#pragma unroll
    for (int k = 0; k < 8; k++) {
        int idx = k * 128 + t;
        int r = idx >> 4;
        int c4 = idx & 15;
        float4 v = ((const float4*)(X + (size_t)(rowBase + r) * 64))[c4];
        Xs[r][c4 * 4 + 0] = v.x; Xs[r][c4 * 4 + 1] = v.y;
        Xs[r][c4 * 4 + 2] = v.z; Xs[r][c4 * 4 + 3] = v.w;
    }
    __syncthreads();

    int r0 = (t >> 3) * 4;
    int c0 = (t & 7) * 8;
    float acc[4][8];
#pragma unroll
    for (int i = 0; i < 4; i++)
#pragma unroll
        for (int j = 0; j < 8; j++) acc[i][j] = 0.f;

#pragma unroll 8
    for (int k = 0; k < 64; k++) {
        float av[4];
        av[0] = Xs[r0 + 0][k]; av[1] = Xs[r0 + 1][k];
        av[2] = Xs[r0 + 2][k]; av[3] = Xs[r0 + 3][k];
        float4 w0 = *(const float4*)&Ws[k][c0];
        float4 w1 = *(const float4*)&Ws[k][c0 + 4];
        float wv[8] = {w0.x, w0.y, w0.z, w0.w, w1.x, w1.y, w1.z, w1.w};
#pragma unroll
        for (int i = 0; i < 4; i++)
#pragma unroll
            for (int j = 0; j < 8; j++) acc[i][j] += av[i] * wv[j];
    }

#pragma unroll
    for (int i = 0; i < 4; i++) {
        float* out = g_bufB + (size_t)(rowBase + r0 + i) * 64 + c0;
        *(float4*)(out + 0) = make_float4(acc[i][0], acc[i][1], acc[i][2], acc[i][3]);
        *(float4*)(out + 4) = make_float4(acc[i][4], acc[i][5], acc[i][6], acc[i][7]);
    }
}

// ---------------------------------------------------------------------------
// GCN aggregation: warp per dst node, cooperative slot loading.
//   h[d] = relu( dis[d]*sum_e xw[src_e]*dis[src_e] + xw[d]*dis[d]^2 + b )
// Epilogue: g_swdis[d] = (h[d].Wp, dis[d])
// ---------------------------------------------------------------------------
__global__ __launch_bounds__(256) void k_conv(const float* __restrict__ bias,
                                              const float* __restrict__ Wp, int ntot) {
    int w = (blockIdx.x * blockDim.x + threadIdx.x) >> 5;
    int lane = threadIdx.x & 31;
    if (w >= ntot) return;
    int start = g_rowptr[w], len = g_deg[w];
    const float2* __restrict__ xw2 = (const float2*)g_bufB;
    float2 acc = make_float2(0.f, 0.f);
    for (int e0 = 0; e0 < len; e0 += 32) {
        int m = len - e0; if (m > 32) m = 32;
        int slot = (lane < m) ? g_slots[start + e0 + lane] : 0;
        float wdis = (lane < m) ? g_dis[slot] : 0.f;
        for (int e = 0; e < m; e++) {
            int s   = __shfl_sync(0xffffffffu, slot, e);
            float d = __shfl_sync(0xffffffffu, wdis, e);
            float2 v = xw2[(size_t)s * 32 + lane];
            acc.x += v.x * d; acc.y += v.y * d;
        }
    }
    float dd = g_dis[w];
    float2 self = xw2[(size_t)w * 32 + lane];
    float hx = fmaxf(acc.x * dd + self.x * dd * dd + bias[2 * lane], 0.f);
    float hy = fmaxf(acc.y * dd + self.y * dd * dd + bias[2 * lane + 1], 0.f);
    ((float2*)g_bufC)[(size_t)w * 32 + lane] = make_float2(hx, hy);
    float p = hx * Wp[2 * lane] + hy * Wp[2 * lane + 1];
#pragma unroll
    for (int o = 16; o > 0; o >>= 1) p += __shfl_down_sync(0xffffffffu, p, o);
    if (lane == 0) g_swdis[w] = make_float2(p, dd);
}

// ---------------------------------------------------------------------------
// Fused score-GCN + per-graph top-k select. One block (512 thr) per graph.
// Matches jax.lax.top_k set semantics incl. index-order tie-break.
// Writes g_perm / g_newidx / g_tanh; block 0 zeroes g_ecount[ec_clear].
// ---------------------------------------------------------------------------
__device__ __forceinline__ void scan1024_excl(int* s) {
    int t = threadIdx.x;
    for (int d = 1; d < 1024; d <<= 1) {
        int i = (t + 1) * (d << 1) - 1;
        if (i < 1024) s[i] += s[i - d];
        __syncthreads();
    }
    if (t == 0) s[1023] = 0;
    __syncthreads();
    for (int d = 512; d >= 1; d >>= 1) {
        int i = (t + 1) * (d << 1) - 1;
        if (i < 1024) { int tmp = s[i - d]; s[i - d] = s[i]; s[i] += tmp; }
        __syncthreads();
    }
}

__global__ __launch_bounds__(512) void k_scoresel(const float* __restrict__ bp,
                                                  int ncur, int ksel, int ec_clear) {
    __shared__ float ssort[1024];
    __shared__ float sorig[1024];
    __shared__ int   sscan[1024];
    __shared__ int   s_g;
    int g = blockIdx.x, t = threadIdx.x;
    if (ec_clear >= 0 && g == 0 && t == 0) g_ecount[ec_clear] = 0;
    int base = g * ncur;
    float bias = bp[0];
    for (int i = t; i < 1024; i += 512) {
        float v = -INFINITY;
        if (i < ncur) {
            int nid = base + i;
            int st = g_rowptr[nid], ln = g_deg[nid];
            float s = 0.f;
            for (int e = 0; e < ln; e++) {
                int sr = g_slots[st + e];
                float2 sd = g_swdis[sr];
                s += sd.x * sd.y;
            }
            float2 self = g_swdis[nid];
            float d = self.y;
            v = d * s + self.x * d * d + bias;
        }
        ssort[i] = v; sorig[i] = v;
    }
    if (t == 0) s_g = 0;
    __syncthreads();
    // bitonic sort descending (1024 elements)
    for (int kk = 2; kk <= 1024; kk <<= 1) {
        for (int j = kk >> 1; j > 0; j >>= 1) {
            for (int i = t; i < 1024; i += 512) {
                int ixj = i ^ j;
                if (ixj > i) {
                    float a = ssort[i], b = ssort[ixj];
                    bool up = ((i & kk) == 0);
                    if (up ? (a < b) : (a > b)) { ssort[i] = b; ssort[ixj] = a; }
                }
            }
            __syncthreads();
        }
    }
    float thr = ssort[ksel - 1];
    int cg = 0;
    for (int i = t; i < 1024; i += 512) if (sorig[i] > thr) cg++;
    atomicAdd(&s_g, cg);
    __syncthreads();
    int need_eq = ksel - s_g;
    for (int i = t; i < 1024; i += 512)
        sscan[i] = (i < ncur && sorig[i] == thr) ? 1 : 0;
    __syncthreads();
    scan1024_excl(sscan);
    int i0 = t, i1 = t + 512;
    float v0 = sorig[i0], v1 = sorig[i1];
    int sel0 = (i0 < ncur) && (v0 > thr || (v0 == thr && sscan[i0] < need_eq));
    int sel1 = (i1 < ncur) && (v1 > thr || (v1 == thr && sscan[i1] < need_eq));
    __syncthreads();
    sscan[i0] = sel0; sscan[i1] = sel1;
    __syncthreads();
    scan1024_excl(sscan);
    if (i0 < ncur) {
        int old = base + i0;
        if (sel0) {
            int np = g * ksel + sscan[i0];
            g_newidx[old] = np; g_perm[np] = old; g_tanh[np] = tanhf(v0);
        } else g_newidx[old] = -1;
    }
    if (i1 < ncur) {
        int old = base + i1;
        if (sel1) {
            int np = g * ksel + sscan[i1];
            g_newidx[old] = np; g_perm[np] = old; g_tanh[np] = tanhf(v1);
        } else g_newidx[old] = -1;
    }
}

// ---------------------------------------------------------------------------
// Fused pool + readout: block per graph. Gathers bufC[perm]*tanh, optionally
// stores to bufA (next conv input), accumulates per-graph max & mean into g_z,
// and clears g_deg for the next layer's node set.
// ---------------------------------------------------------------------------
__global__ __launch_bounds__(256) void k_poolread(int knew, int acc, int store) {
    int g = blockIdx.x, t = threadIdx.x;
    int f = t & 63, rq = t >> 6;
    float mx = -INFINITY, sm = 0.f;
    int base = g * knew;
    for (int j = rq; j < knew; j += 4) {
        int nid = base + j;
        int old = g_perm[nid];
        float tg = g_tanh[nid];
        float v = g_bufC[(size_t)old * 64 + f] * tg;
        if (store) g_bufA[(size_t)nid * 64 + f] = v;
        mx = fmaxf(mx, v); sm += v;
    }
    if (store) for (int j = t; j < knew; j += 256) g_deg[base + j] = 0;
    __shared__ float smx[4][64], ssm[4][64];
    smx[rq][f] = mx; ssm[rq][f] = sm;
    __syncthreads();
    if (rq == 0) {
        mx = fmaxf(fmaxf(smx[0][f], smx[1][f]), fmaxf(smx[2][f], smx[3][f]));
        sm = ssm[0][f] + ssm[1][f] + ssm[2][f] + ssm[3][f];
        float mean = sm / (float)knew;
        if (acc) { g_z[g * 128 + f] += mx; g_z[g * 128 + 64 + f] += mean; }
        else     { g_z[g * 128 + f]  = mx; g_z[g * 128 + 64 + f]  = mean; }
    }
}

// ---------------------------------------------------------------------------
// remap + compact edges for next layer; counts next-layer degrees; resets scan
// state for the next k_scan.
// ---------------------------------------------------------------------------
__global__ void k_remap(const int* srcp, const int* dstp, int insel,
                        int cw, int fixcnt, int outsel) {
    int gt = blockIdx.x * blockDim.x + threadIdx.x;
    if (gt < 256) g_tstate[gt] = 0;
    if (gt == 256) g_tix = 0;
    const int* __restrict__ src = pick_list_src(srcp, insel);
    const int* __restrict__ dst = pick_list_dst(dstp, insel);
    int* os = outsel ? g_srcB : g_srcA;
    int* od = outsel ? g_dstB : g_dstA;
    int cnt = (cw >= 0) ? g_ecount[cw] : fixcnt;
    int stride = gridDim.x * blockDim.x;
    for (int i = gt; i < cnt; i += stride) {
        int ns = g_newidx[src[i]];
        int nd = g_newidx[dst[i]];
        if ((ns | nd) >= 0) {
            int p = atomicAdd(&g_ecount[outsel], 1);
            os[p] = ns; od[p] = nd;
            atomicAdd(&g_deg[nd], 1);
        }
    }
}

// ---------------------------------------------------------------------------
// MLP head + log_softmax, one block (128 thr) per graph
// ---------------------------------------------------------------------------
__global__ __launch_bounds__(128) void k_mlp(const float* __restrict__ L1w,
                                             const float* __restrict__ L1b,
                                             const float* __restrict__ L2w,
                                             const float* __restrict__ L2b,
                                             const float* __restrict__ L3w,
                                             const float* __restrict__ L3b,
                                             float* __restrict__ out) {
    int g = blockIdx.x, t = threadIdx.x;
    __shared__ float zs[128], h1[64], h2[32], lg[10], lse;
    zs[t] = g_z[g * 128 + t];
    __syncthreads();
    if (t < 64) {
        float a = L1b[t];
        for (int k = 0; k < 128; k++) a += zs[k] * L1w[k * 64 + t];
        h1[t] = fmaxf(a, 0.f);
    }
    __syncthreads();
    if (t < 32) {
        float a = L2b[t];
        for (int k = 0; k < 64; k++) a += h1[k] * L2w[k * 32 + t];
        h2[t] = fmaxf(a, 0.f);
    }
    __syncthreads();
    if (t < 10) {
        float a = L3b[t];
        for (int k = 0; k < 32; k++) a += h2[k] * L3w[k * 10 + t];
        lg[t] = a;
    }
    __syncthreads();
    if (t == 0) {
        float m = lg[0];
        for (int i = 1; i < 10; i++) m = fmaxf(m, lg[i]);
        float s = 0.f;
        for (int i = 0; i < 10; i++) s += expf(lg[i] - m);
        lse = m + logf(s);
    }
    __syncthreads();
    if (t < 10) out[g * 10 + t] = lg[t] - lse;
}

// ---------------------------------------------------------------------------
// Host orchestration
// ---------------------------------------------------------------------------
extern "C" void kernel_launch(void* const* d_in, const int* in_sizes, int n_in,
                              void* d_out, int out_size) {
    const float* x    = (const float*)d_in[0];
    const int*   esrc = (const int*)d_in[1];
    const int*   edst = (const int*)d_in[2];
    const float* W1  = (const float*)d_in[3];
    const float* b1  = (const float*)d_in[4];
    const float* Wp1 = (const float*)d_in[5];
    const float* bp1 = (const float*)d_in[6];
    const float* W2  = (const float*)d_in[7];
    const float* b2  = (const float*)d_in[8];
    const float* Wp2 = (const float*)d_in[9];
    const float* bp2 = (const float*)d_in[10];
    const float* W3  = (const float*)d_in[11];
    const float* b3  = (const float*)d_in[12];
    const float* Wp3 = (const float*)d_in[13];
    const float* bp3 = (const float*)d_in[14];
    const float* L1w = (const float*)d_in[15];
    const float* L1b = (const float*)d_in[16];
    const float* L2w = (const float*)d_in[17];
    const float* L2b = (const float*)d_in[18];
    const float* L3w = (const float*)d_in[19];
    const float* L3b = (const float*)d_in[20];
    float* out = (float*)d_out;

    const int EG = 2048;

    // ---------------- Layer 1 ----------------
    k_clear<<<NT1 / 256, 256>>>();
    k_deg<<<EG, 256>>>(edst, NE);
    k_gemm<<<NT1 / 64, 128>>>(x, W1, NT1);
    k_scan<<<NT1 / 1024, 256>>>(NT1);
    k_fill<<<EG, 256>>>(esrc, edst, 0, -1, NE);
    k_conv<<<NT1 / 8, 256>>>(b1, Wp1, NT1);
    k_scoresel<<<GB, 512>>>(bp1, NPG, K1, 0);
    k_poolread<<<GB, 256>>>(K1, 0, 1);        // clears g_deg[0..NT2)
    k_remap<<<EG, 256>>>(esrc, edst, 0, -1, NE, 0);  // counts deg, resets scan state

    // ---------------- Layer 2 ----------------
    k_scan<<<(NT2 + 1023) / 1024, 256>>>(NT2);
    k_fill<<<EG, 256>>>(nullptr, nullptr, 0, 0, 0);
    k_gemm<<<NT2 / 64, 128>>>(nullptr, W2, NT2);
    k_conv<<<NT2 / 8, 256>>>(b2, Wp2, NT2);
    k_scoresel<<<GB, 512>>>(bp2, K1, K2, 1);
    k_poolread<<<GB, 256>>>(K2, 1, 1);        // clears g_deg[0..NT3)
    k_remap<<<EG, 256>>>(nullptr, nullptr, 0, 0, 0, 1);

    // ---------------- Layer 3 ----------------
    k_scan<<<NT3 / 1024, 256>>>(NT3);
    k_fill<<<EG, 256>>>(nullptr, nullptr, 1, 1, 0);
    k_gemm<<<NT3 / 64, 128>>>(nullptr, W3, NT3);
    k_conv<<<NT3 / 8, 256>>>(b3, Wp3, NT3);
    k_scoresel<<<GB, 512>>>(bp3, K2, K3, -1);
    k_poolread<<<GB, 256>>>(K3, 1, 0);

    // ---------------- MLP head ----------------
    k_mlp<<<GB, 128>>>(L1w, L1b, L2w, L2b, L3w, L3b, out);
}